// round 1
// baseline (speedup 1.0000x reference)
#include <cuda_runtime.h>
#include <math.h>

// ---------------- problem constants ----------------
#define N0 120000
#define N1 24000
#define N2 6000
#define D  256
#define H1 8
#define C1 64
#define HC1 (H1*C1)     // 512
#define H2 8
#define C2 256
#define HC2 (H2*C2)     // 2048
#define E1MAX 384000
#define E2MAX 96000
#define NEG_SLOPE 0.2f

// ---------------- scratch (static device globals; no allocation) ----------------
__device__ float g_h1[(size_t)N0 * HC1];     // 245.8 MB
__device__ float g_x1[(size_t)N1 * HC1];     //  49.2 MB
__device__ float g_h2[(size_t)N1 * HC2];     // 196.6 MB
__device__ float g_as1[(size_t)N0 * H1];
__device__ float g_ad1[(size_t)N1 * H1];
__device__ float g_as2[(size_t)N1 * H2];
__device__ float g_ad2[(size_t)N2 * H2];
__device__ int g_deg1[N1];
__device__ int g_rp1[N1 + 1];
__device__ int g_cur1[N1];
__device__ int g_col1[E1MAX];
__device__ int g_deg2[N2];
__device__ int g_rp2[N2 + 1];
__device__ int g_cur2[N2];
__device__ int g_col2[E2MAX];

// ---------------- fp32 tiled GEMM: C[M,N] = A[M,K] @ B[K,N] ----------------
// BM=BN=128, BK=16, 256 threads, 8x8 per thread. N%128==0, K%16==0, M guarded.
__global__ __launch_bounds__(256) void sgemm128(
    const float* __restrict__ A, const float* __restrict__ B,
    float* __restrict__ C, int M, int N, int K)
{
    __shared__ float As[16][128];
    __shared__ float Bs[16][128];
    const int tid = threadIdx.x;
    const int bm = blockIdx.y * 128;
    const int bn = blockIdx.x * 128;
    const int tx = tid & 15;        // 16 cols of 8
    const int ty = tid >> 4;        // 16 rows of 8
    const int arow = tid >> 2;          // 0..63
    const int acol = (tid & 3) << 2;    // 0,4,8,12
    const int brow = tid >> 5;          // 0..7
    const int bcol = (tid & 31) << 2;   // 0..124

    float acc[8][8];
#pragma unroll
    for (int i = 0; i < 8; i++)
#pragma unroll
        for (int j = 0; j < 8; j++) acc[i][j] = 0.f;

    for (int k0 = 0; k0 < K; k0 += 16) {
#pragma unroll
        for (int r = 0; r < 2; r++) {
            int m = arow + r * 64;
            float4 v = make_float4(0.f, 0.f, 0.f, 0.f);
            if (bm + m < M)
                v = *reinterpret_cast<const float4*>(A + (size_t)(bm + m) * K + k0 + acol);
            As[acol + 0][m] = v.x; As[acol + 1][m] = v.y;
            As[acol + 2][m] = v.z; As[acol + 3][m] = v.w;
        }
#pragma unroll
        for (int r = 0; r < 2; r++) {
            int kk = brow + r * 8;
            float4 v = *reinterpret_cast<const float4*>(B + (size_t)(k0 + kk) * N + bn + bcol);
            *reinterpret_cast<float4*>(&Bs[kk][bcol]) = v;
        }
        __syncthreads();
#pragma unroll
        for (int kk = 0; kk < 16; kk++) {
            float ra[8], rb[8];
#pragma unroll
            for (int i = 0; i < 8; i++) ra[i] = As[kk][ty * 8 + i];
#pragma unroll
            for (int j = 0; j < 8; j++) rb[j] = Bs[kk][tx * 8 + j];
#pragma unroll
            for (int i = 0; i < 8; i++)
#pragma unroll
                for (int j = 0; j < 8; j++) acc[i][j] = fmaf(ra[i], rb[j], acc[i][j]);
        }
        __syncthreads();
    }
#pragma unroll
    for (int i = 0; i < 8; i++) {
        int m = bm + ty * 8 + i;
        if (m < M) {
            float* cp = C + (size_t)m * N + bn + tx * 8;
            *reinterpret_cast<float4*>(cp)     = make_float4(acc[i][0], acc[i][1], acc[i][2], acc[i][3]);
            *reinterpret_cast<float4*>(cp + 4) = make_float4(acc[i][4], acc[i][5], acc[i][6], acc[i][7]);
        }
    }
}

// ---------------- attention score: a[n,h] = sum_c h[n,h*C+c]*att[h*C+c] ----------------
// one block per node, warp w handles head w (H=8 -> 256 threads)
__global__ __launch_bounds__(256) void ascore_kernel(
    const float* __restrict__ h, const float* __restrict__ attS,
    const float* __restrict__ attD, float* __restrict__ aS, float* __restrict__ aD,
    int N, int Ndst, int HC, int C)
{
    int n = blockIdx.x;
    int warp = threadIdx.x >> 5;
    int lane = threadIdx.x & 31;
    const float* hp = h + (size_t)n * HC + warp * C;
    const float* sp = attS + warp * C;
    const float* dp = attD + warp * C;
    float vs = 0.f, vd = 0.f;
    for (int c = lane; c < C; c += 32) {
        float x = hp[c];
        vs = fmaf(x, sp[c], vs);
        vd = fmaf(x, dp[c], vd);
    }
#pragma unroll
    for (int off = 16; off > 0; off >>= 1) {
        vs += __shfl_xor_sync(0xffffffffu, vs, off);
        vd += __shfl_xor_sync(0xffffffffu, vd, off);
    }
    if (lane == 0) {
        aS[n * 8 + warp] = vs;
        if (n < Ndst) aD[n * 8 + warp] = vd;
    }
}

// ---------------- CSR build ----------------
__global__ void zero_int_kernel(int* p, int n) {
    int i = blockIdx.x * blockDim.x + threadIdx.x;
    if (i < n) p[i] = 0;
}
__global__ void hist_kernel(const int* __restrict__ dst, int E, int* __restrict__ deg) {
    int i = blockIdx.x * blockDim.x + threadIdx.x;
    if (i < E) atomicAdd(&deg[dst[i]], 1);
}
// single block, 1024 threads; exclusive scan of deg -> rowptr[0..n], cursor copy
__global__ __launch_bounds__(1024) void scan_kernel(
    const int* __restrict__ deg, int* __restrict__ rowptr, int* __restrict__ cursor, int n)
{
    __shared__ int sh[1024];
    int t = threadIdx.x;
    int per = (n + 1023) >> 10;
    int lo = t * per;
    int hi = min(lo + per, n);
    int s = 0;
    for (int i = lo; i < hi; i++) s += deg[i];
    sh[t] = s;
    __syncthreads();
    for (int off = 1; off < 1024; off <<= 1) {
        int v = (t >= off) ? sh[t - off] : 0;
        __syncthreads();
        sh[t] += v;
        __syncthreads();
    }
    int run = (t == 0) ? 0 : sh[t - 1];
    for (int i = lo; i < hi; i++) {
        rowptr[i] = run;
        cursor[i] = run;
        run += deg[i];
    }
    if (t == 0) rowptr[n] = sh[1023];
}
__global__ void scatter_kernel(const int* __restrict__ src, const int* __restrict__ dst,
                               int E, int* __restrict__ cursor, int* __restrict__ col)
{
    int i = blockIdx.x * blockDim.x + threadIdx.x;
    if (i < E) {
        int p = atomicAdd(&cursor[dst[i]], 1);
        col[p] = src[i];
    }
}

// ---------------- layer 1 fused softmax + aggregate + bias + ELU ----------------
// one block (128 thr) per dst node; thread t handles 4 channels [4t,4t+4), head=t/16
__global__ __launch_bounds__(128) void agg1_kernel(
    const float* __restrict__ h1, const float* __restrict__ asrc,
    const float* __restrict__ adst, const int* __restrict__ rowptr,
    const int* __restrict__ col, const float* __restrict__ bias,
    float* __restrict__ x1)
{
    const int n = blockIdx.x;
    const int t = threadIdx.x;
    const int warp = t >> 5, lane = t & 31;
    __shared__ float sadst[8], sm[8], ss[8];
    __shared__ float red[4][8];
    __shared__ float salpha[16 * 8];
    __shared__ int scol[16];

    const int start = rowptr[n], end = rowptr[n + 1];
    if (t < 8) sadst[t] = adst[n * 8 + t];
    __syncthreads();

    // pass 1: per-head max
    float lm[8];
#pragma unroll
    for (int h = 0; h < 8; h++) lm[h] = -1e30f;
    for (int j = start + t; j < end; j += 128) {
        const float* ap = asrc + (size_t)col[j] * 8;
#pragma unroll
        for (int h = 0; h < 8; h++) {
            float e = ap[h] + sadst[h];
            e = e > 0.f ? e : NEG_SLOPE * e;
            lm[h] = fmaxf(lm[h], e);
        }
    }
#pragma unroll
    for (int h = 0; h < 8; h++)
#pragma unroll
        for (int off = 16; off > 0; off >>= 1)
            lm[h] = fmaxf(lm[h], __shfl_xor_sync(0xffffffffu, lm[h], off));
    if (lane == 0)
#pragma unroll
        for (int h = 0; h < 8; h++) red[warp][h] = lm[h];
    __syncthreads();
    if (t < 8) sm[t] = fmaxf(fmaxf(red[0][t], red[1][t]), fmaxf(red[2][t], red[3][t]));
    __syncthreads();

    // pass 2: per-head denom
    float lsum[8];
#pragma unroll
    for (int h = 0; h < 8; h++) lsum[h] = 0.f;
    for (int j = start + t; j < end; j += 128) {
        const float* ap = asrc + (size_t)col[j] * 8;
#pragma unroll
        for (int h = 0; h < 8; h++) {
            float e = ap[h] + sadst[h];
            e = e > 0.f ? e : NEG_SLOPE * e;
            lsum[h] += expf(e - sm[h]);
        }
    }
#pragma unroll
    for (int h = 0; h < 8; h++)
#pragma unroll
        for (int off = 16; off > 0; off >>= 1)
            lsum[h] += __shfl_xor_sync(0xffffffffu, lsum[h], off);
    if (lane == 0)
#pragma unroll
        for (int h = 0; h < 8; h++) red[warp][h] = lsum[h];
    __syncthreads();
    if (t < 8) ss[t] = red[0][t] + red[1][t] + red[2][t] + red[3][t];
    __syncthreads();

    // pass 3: chunked alpha + accumulate
    float acc0 = 0.f, acc1 = 0.f, acc2 = 0.f, acc3 = 0.f;
    const int head = t >> 4;
    const int c4 = t << 2;
    for (int base = start; base < end; base += 16) {
        int cnt = min(16, end - base);
        if (t < cnt) scol[t] = col[base + t];
        if (t < cnt * 8) {
            int j = base + (t >> 3);
            int h = t & 7;
            float e = asrc[(size_t)col[j] * 8 + h] + sadst[h];
            e = e > 0.f ? e : NEG_SLOPE * e;
            salpha[t] = expf(e - sm[h]) / ss[h];
        }
        __syncthreads();
        for (int q = 0; q < cnt; q++) {
            int s = scol[q];
            float a = salpha[q * 8 + head];
            float4 v = *reinterpret_cast<const float4*>(h1 + (size_t)s * HC1 + c4);
            acc0 = fmaf(a, v.x, acc0);
            acc1 = fmaf(a, v.y, acc1);
            acc2 = fmaf(a, v.z, acc2);
            acc3 = fmaf(a, v.w, acc3);
        }
        __syncthreads();
    }
    // bias + ELU
    float o[4] = {acc0, acc1, acc2, acc3};
#pragma unroll
    for (int i = 0; i < 4; i++) {
        float v = o[i] + bias[c4 + i];
        v = v > 0.f ? v : expm1f(v);
        x1[(size_t)n * HC1 + c4 + i] = v;
    }
}

// ---------------- layer 2 fused softmax + aggregate + head-mean + bias ----------------
// one block (256 thr) per dst node; thread t = channel c, acc over 8 heads
__global__ __launch_bounds__(256) void agg2_kernel(
    const float* __restrict__ h2, const float* __restrict__ asrc,
    const float* __restrict__ adst, const int* __restrict__ rowptr,
    const int* __restrict__ col, const float* __restrict__ bias,
    float* __restrict__ out)
{
    const int n = blockIdx.x;
    const int t = threadIdx.x;
    const int warp = t >> 5, lane = t & 31;
    __shared__ float sadst[8], sm[8], ss[8];
    __shared__ float red[8][8];
    __shared__ float salpha[32 * 8];
    __shared__ int scol[32];

    const int start = rowptr[n], end = rowptr[n + 1];
    if (t < 8) sadst[t] = adst[n * 8 + t];
    __syncthreads();

    float lm[8];
#pragma unroll
    for (int h = 0; h < 8; h++) lm[h] = -1e30f;
    for (int j = start + t; j < end; j += 256) {
        const float* ap = asrc + (size_t)col[j] * 8;
#pragma unroll
        for (int h = 0; h < 8; h++) {
            float e = ap[h] + sadst[h];
            e = e > 0.f ? e : NEG_SLOPE * e;
            lm[h] = fmaxf(lm[h], e);
        }
    }
#pragma unroll
    for (int h = 0; h < 8; h++)
#pragma unroll
        for (int off = 16; off > 0; off >>= 1)
            lm[h] = fmaxf(lm[h], __shfl_xor_sync(0xffffffffu, lm[h], off));
    if (lane == 0)
#pragma unroll
        for (int h = 0; h < 8; h++) red[warp][h] = lm[h];
    __syncthreads();
    if (t < 8) {
        float m = red[0][t];
#pragma unroll
        for (int w = 1; w < 8; w++) m = fmaxf(m, red[w][t]);
        sm[t] = m;
    }
    __syncthreads();

    float lsum[8];
#pragma unroll
    for (int h = 0; h < 8; h++) lsum[h] = 0.f;
    for (int j = start + t; j < end; j += 256) {
        const float* ap = asrc + (size_t)col[j] * 8;
#pragma unroll
        for (int h = 0; h < 8; h++) {
            float e = ap[h] + sadst[h];
            e = e > 0.f ? e : NEG_SLOPE * e;
            lsum[h] += expf(e - sm[h]);
        }
    }
#pragma unroll
    for (int h = 0; h < 8; h++)
#pragma unroll
        for (int off = 16; off > 0; off >>= 1)
            lsum[h] += __shfl_xor_sync(0xffffffffu, lsum[h], off);
    if (lane == 0)
#pragma unroll
        for (int h = 0; h < 8; h++) red[warp][h] = lsum[h];
    __syncthreads();
    if (t < 8) {
        float s = 0.f;
#pragma unroll
        for (int w = 0; w < 8; w++) s += red[w][t];
        ss[t] = s;
    }
    __syncthreads();

    float acc[8];
#pragma unroll
    for (int h = 0; h < 8; h++) acc[h] = 0.f;
    for (int base = start; base < end; base += 32) {
        int cnt = min(32, end - base);
        if (t < cnt) scol[t] = col[base + t];
        if (t < cnt * 8) {
            int j = base + (t >> 3);
            int h = t & 7;
            float e = asrc[(size_t)col[j] * 8 + h] + sadst[h];
            e = e > 0.f ? e : NEG_SLOPE * e;
            salpha[t] = expf(e - sm[h]) / ss[h];
        }
        __syncthreads();
        for (int q = 0; q < cnt; q++) {
            const float* hp = h2 + (size_t)scol[q] * HC2 + t;
#pragma unroll
            for (int h = 0; h < 8; h++)
                acc[h] = fmaf(salpha[q * 8 + h], hp[h * C2], acc[h]);
        }
        __syncthreads();
    }
    float s = 0.f;
#pragma unroll
    for (int h = 0; h < 8; h++) s += acc[h];
    out[(size_t)n * C2 + t] = 0.125f * s + bias[t];
}

// ---------------- host ----------------
extern "C" void kernel_launch(void* const* d_in, const int* in_sizes, int n_in,
                              void* d_out, int out_size)
{
    const float* x        = (const float*)d_in[0];
    const int*   src1     = (const int*)d_in[1];
    const int*   dst1     = (const int*)d_in[2];
    const int*   src2     = (const int*)d_in[3];
    const int*   dst2     = (const int*)d_in[4];
    const float* W1       = (const float*)d_in[5];
    const float* att_src1 = (const float*)d_in[6];
    const float* att_dst1 = (const float*)d_in[7];
    const float* b1       = (const float*)d_in[8];
    const float* W2       = (const float*)d_in[9];
    const float* att_src2 = (const float*)d_in[10];
    const float* att_dst2 = (const float*)d_in[11];
    const float* b2       = (const float*)d_in[12];
    float* out = (float*)d_out;

    const int E1 = in_sizes[1];
    const int E2 = in_sizes[3];

    float *h1, *x1, *h2, *as1, *ad1, *as2, *ad2;
    int *deg1, *rp1, *cur1, *col1, *deg2, *rp2, *cur2, *col2;
    cudaGetSymbolAddress((void**)&h1, g_h1);
    cudaGetSymbolAddress((void**)&x1, g_x1);
    cudaGetSymbolAddress((void**)&h2, g_h2);
    cudaGetSymbolAddress((void**)&as1, g_as1);
    cudaGetSymbolAddress((void**)&ad1, g_ad1);
    cudaGetSymbolAddress((void**)&as2, g_as2);
    cudaGetSymbolAddress((void**)&ad2, g_ad2);
    cudaGetSymbolAddress((void**)&deg1, g_deg1);
    cudaGetSymbolAddress((void**)&rp1, g_rp1);
    cudaGetSymbolAddress((void**)&cur1, g_cur1);
    cudaGetSymbolAddress((void**)&col1, g_col1);
    cudaGetSymbolAddress((void**)&deg2, g_deg2);
    cudaGetSymbolAddress((void**)&rp2, g_rp2);
    cudaGetSymbolAddress((void**)&cur2, g_cur2);
    cudaGetSymbolAddress((void**)&col2, g_col2);

    // ---- layer 1 ----
    {
        dim3 grid(HC1 / 128, (N0 + 127) / 128);
        sgemm128<<<grid, 256>>>(x, W1, h1, N0, HC1, D);
    }
    ascore_kernel<<<N0, 256>>>(h1, att_src1, att_dst1, as1, ad1, N0, N1, HC1, C1);

    zero_int_kernel<<<(N1 + 255) / 256, 256>>>(deg1, N1);
    hist_kernel<<<(E1 + 255) / 256, 256>>>(dst1, E1, deg1);
    scan_kernel<<<1, 1024>>>(deg1, rp1, cur1, N1);
    scatter_kernel<<<(E1 + 255) / 256, 256>>>(src1, dst1, E1, cur1, col1);

    agg1_kernel<<<N1, 128>>>(h1, as1, ad1, rp1, col1, b1, x1);

    // ---- layer 2 ----
    {
        dim3 grid(HC2 / 128, (N1 + 127) / 128);
        sgemm128<<<grid, 256>>>(x1, W2, h2, N1, HC2, HC1);
    }
    ascore_kernel<<<N1, 256>>>(h2, att_src2, att_dst2, as2, ad2, N1, N2, HC2, C2);

    zero_int_kernel<<<(N2 + 255) / 256, 256>>>(deg2, N2);
    hist_kernel<<<(E2 + 255) / 256, 256>>>(dst2, E2, deg2);
    scan_kernel<<<1, 1024>>>(deg2, rp2, cur2, N2);
    scatter_kernel<<<(E2 + 255) / 256, 256>>>(src2, dst2, E2, cur2, col2);

    agg2_kernel<<<N2, 256>>>(h2, as2, ad2, rp2, col2, b2, out);

    (void)n_in; (void)out_size;
}

// round 3
// speedup vs baseline: 2.0617x; 2.0617x over previous
#include <cuda_runtime.h>
#include <cuda_bf16.h>
#include <cstdint>
#include <math.h>

// ---------------- problem constants ----------------
#define N0 120000
#define N1 24000
#define N2 6000
#define D  256
#define H1 8
#define C1 64
#define HC1 (H1*C1)     // 512
#define H2 8
#define C2 256
#define HC2 (H2*C2)     // 2048
#define E1MAX 384000
#define E2MAX 96000
#define NEG_SLOPE 0.2f

#define KP1 (3*D)       // 768   split-K' for GEMM1
#define KP2 (3*HC1)     // 1536  split-K' for GEMM2

// ---------------- scratch (static device globals; no allocation) ----------------
__device__ float g_h1[(size_t)N0 * HC1];     // 245.8 MB
__device__ float g_x1[(size_t)N1 * HC1];     //  49.2 MB
__device__ float g_h2[(size_t)N1 * HC2];     // 196.6 MB
__device__ float g_as1[(size_t)N0 * H1];
__device__ float g_ad1[(size_t)N1 * H1];
__device__ float g_as2[(size_t)N1 * H2];
__device__ float g_ad2[(size_t)N2 * H2];
__device__ int g_deg1[N1];
__device__ int g_rp1[N1 + 1];
__device__ int g_cur1[N1];
__device__ int g_col1[E1MAX];
__device__ int g_deg2[N2];
__device__ int g_rp2[N2 + 1];
__device__ int g_cur2[N2];
__device__ int g_col2[E2MAX];
// split-precision bf16 operands
__device__ __nv_bfloat16 g_a1p[(size_t)N0 * KP1];   // 184.3 MB
__device__ __nv_bfloat16 g_b1p[(size_t)HC1 * KP1];  //  0.8 MB
__device__ __nv_bfloat16 g_a2p[(size_t)N1 * KP2];   //  73.7 MB
__device__ __nv_bfloat16 g_b2p[(size_t)HC2 * KP2];  //  6.3 MB

// ================= PTX helpers (sm_80-era generic: OK on non-'a' targets) =================
__device__ __forceinline__ uint32_t smem_u32(const void* p) {
    uint32_t a;
    asm("{ .reg .u64 t; cvta.to.shared.u64 t, %1; cvt.u32.u64 %0, t; }" : "=r"(a) : "l"(p));
    return a;
}
#define CP_ASYNC16(sp, gp) \
    asm volatile("cp.async.cg.shared.global [%0], [%1], 16;" :: "r"(sp), "l"(gp) : "memory")
#define CP_COMMIT() asm volatile("cp.async.commit_group;" ::: "memory")
#define CP_WAIT(n)  asm volatile("cp.async.wait_group %0;" :: "n"(n) : "memory")
#define LDMX4(r, addr) \
    asm volatile("ldmatrix.sync.aligned.m8n8.x4.shared.b16 {%0,%1,%2,%3}, [%4];" \
        : "=r"((r)[0]), "=r"((r)[1]), "=r"((r)[2]), "=r"((r)[3]) : "r"(addr))
#define MMA16816(d, a, b0v, b1v) \
    asm volatile("mma.sync.aligned.m16n8k16.row.col.f32.bf16.bf16.f32 " \
        "{%0,%1,%2,%3}, {%4,%5,%6,%7}, {%8,%9}, {%0,%1,%2,%3};" \
        : "+f"((d)[0]), "+f"((d)[1]), "+f"((d)[2]), "+f"((d)[3]) \
        : "r"((a)[0]), "r"((a)[1]), "r"((a)[2]), "r"((a)[3]), "r"(b0v), "r"(b1v))

// ================= bf16 mma.sync GEMM: C[M,Nfull] = A[M,Kp] * B[Nfull,Kp]^T =================
// CTA tile 128x128, BK=64 (128B rows, SW128 swizzle), 256 thr = 4(M) x 2(N) warps,
// warp tile 32x64, 3-stage cp.async pipeline. M guarded via row clamp + store guard.
#define STAGE_BYTES 32768          // A 16KB + B 16KB
#define SMEM_GEMM   (3 * STAGE_BYTES)

__device__ __forceinline__ void gemm_load_stage(
    const __nv_bfloat16* __restrict__ A, const __nv_bfloat16* __restrict__ B,
    int M, int Kp, int bm, int bn, int c, uint32_t stbase, int tid)
{
    const int r0 = tid >> 3;       // 0..31
    const int kseg = tid & 7;      // 16B segment in 128B row
    const uint32_t abase = stbase;
    const uint32_t bbase = stbase + 16384;
#pragma unroll
    for (int i = 0; i < 4; i++) {
        int row = r0 + i * 32;
        int grow = bm + row; if (grow >= M) grow = M - 1;
        const void* gp = (const void*)(A + (size_t)grow * Kp + c * 64 + kseg * 8);
        uint32_t sp = abase + (uint32_t)(row * 128) + ((uint32_t)(kseg * 16) ^ (uint32_t)((row & 7) << 4));
        CP_ASYNC16(sp, gp);
    }
#pragma unroll
    for (int i = 0; i < 4; i++) {
        int row = r0 + i * 32;
        const void* gp = (const void*)(B + (size_t)(bn + row) * Kp + c * 64 + kseg * 8);
        uint32_t sp = bbase + (uint32_t)(row * 128) + ((uint32_t)(kseg * 16) ^ (uint32_t)((row & 7) << 4));
        CP_ASYNC16(sp, gp);
    }
}

__global__ __launch_bounds__(256, 2) void gemm_mma(
    const __nv_bfloat16* __restrict__ A, const __nv_bfloat16* __restrict__ B,
    float* __restrict__ C, int M, int Nfull, int Kp)
{
    extern __shared__ __align__(1024) char smem[];
    const uint32_t sb = smem_u32(smem);
    const int tid = threadIdx.x;
    const int lane = tid & 31, wid = tid >> 5;
    const int wm = wid & 3, wn = wid >> 2;          // 4 x 2 warp grid
    const int bm = blockIdx.y * 128, bn = blockIdx.x * 128;

    // ldmatrix lane address components (swizzle term is f(row) only, since kbyte < 128)
    // A frag (m16k16) at (mrow0, k0): lanes 0-7 rows+0 @k0 | 8-15 rows+8 @k0 | 16-23 rows+0 @k0+8 | 24-31 rows+8 @k0+8
    int arow[2], asw[2];
#pragma unroll
    for (int mi = 0; mi < 2; mi++) {
        int r = wm * 32 + mi * 16 + (lane & 7) + ((lane >> 3) & 1) * 8;
        arow[mi] = r * 128;
        asw[mi] = (r & 7) << 4;
    }
    const uint32_t akadd = ((lane >> 4) & 1) * 16;   // bytes
    // B frag pair (two n8 per x4) at (nrow0, k0): lanes 0-7 n+0 @k0 | 8-15 n+0 @k0+8 | 16-23 n+8 @k0 | 24-31 n+8 @k0+8
    int brow[4], bsw[4];
#pragma unroll
    for (int nb = 0; nb < 4; nb++) {
        int r = wn * 64 + nb * 16 + ((lane >> 4) & 1) * 8 + (lane & 7);
        brow[nb] = r * 128;
        bsw[nb] = (r & 7) << 4;
    }
    const uint32_t bkadd = ((lane >> 3) & 1) * 16;   // bytes

    float acc[2][8][4];
#pragma unroll
    for (int mi = 0; mi < 2; mi++)
#pragma unroll
        for (int ni = 0; ni < 8; ni++)
#pragma unroll
            for (int q = 0; q < 4; q++) acc[mi][ni][q] = 0.f;

    const int nch = Kp >> 6;

    gemm_load_stage(A, B, M, Kp, bm, bn, 0, sb, tid); CP_COMMIT();
    gemm_load_stage(A, B, M, Kp, bm, bn, 1, sb + STAGE_BYTES, tid); CP_COMMIT();

    for (int c = 0; c < nch; c++) {
        if (c + 2 < nch) {
            gemm_load_stage(A, B, M, Kp, bm, bn, c + 2, sb + ((c + 2) % 3) * STAGE_BYTES, tid);
            CP_COMMIT();
            CP_WAIT(2);
        } else if (c + 1 < nch) {
            CP_WAIT(1);
        } else {
            CP_WAIT(0);
        }
        __syncthreads();

        const uint32_t abase = sb + (c % 3) * STAGE_BYTES;
        const uint32_t bbase = abase + 16384;
#pragma unroll
        for (int ks = 0; ks < 4; ks++) {
            const uint32_t k0b = ks * 32;   // byte offset of k16 step
            uint32_t af[2][4];
#pragma unroll
            for (int mi = 0; mi < 2; mi++) {
                uint32_t addr = abase + arow[mi] + ((k0b + akadd) ^ (uint32_t)asw[mi]);
                LDMX4(af[mi], addr);
            }
            uint32_t bf[4][4];
#pragma unroll
            for (int nb = 0; nb < 4; nb++) {
                uint32_t addr = bbase + brow[nb] + ((k0b + bkadd) ^ (uint32_t)bsw[nb]);
                LDMX4(bf[nb], addr);
            }
#pragma unroll
            for (int mi = 0; mi < 2; mi++)
#pragma unroll
                for (int ni = 0; ni < 8; ni++) {
                    const int nb = ni >> 1, hf = ni & 1;
                    MMA16816(acc[mi][ni], af[mi], bf[nb][hf * 2], bf[nb][hf * 2 + 1]);
                }
        }
        __syncthreads();
    }

    // epilogue: c0,c1 -> (row = lane>>2, col = 2*(lane&3)+{0,1}); c2,c3 -> row+8
    const int crow0 = bm + wm * 32 + (lane >> 2);
    const int ccol0 = bn + wn * 64 + (lane & 3) * 2;
#pragma unroll
    for (int mi = 0; mi < 2; mi++)
#pragma unroll
        for (int hf = 0; hf < 2; hf++) {
            int row = crow0 + mi * 16 + hf * 8;
            if (row < M) {
                float* cp = C + (size_t)row * Nfull + ccol0;
#pragma unroll
                for (int ni = 0; ni < 8; ni++) {
                    float2 v = make_float2(acc[mi][ni][hf * 2], acc[mi][ni][hf * 2 + 1]);
                    *reinterpret_cast<float2*>(cp + ni * 8) = v;
                }
            }
        }
}

// ---------------- split-precision conversions ----------------
// A' = [hi | lo | hi]  (M x 3K) from fp32 X (M x K)
__global__ void conv_split_kernel(const float* __restrict__ X, __nv_bfloat16* __restrict__ Ap,
                                  int M, int K)
{
    size_t i = (size_t)blockIdx.x * blockDim.x + threadIdx.x;
    int kq = K >> 2;
    size_t total = (size_t)M * kq;
    if (i >= total) return;
    int m = (int)(i / kq);
    int k = (int)(i - (size_t)m * kq) << 2;
    float4 v = *reinterpret_cast<const float4*>(X + (size_t)m * K + k);
    float xs[4] = {v.x, v.y, v.z, v.w};
    __nv_bfloat16 hi[4], lo[4];
#pragma unroll
    for (int j = 0; j < 4; j++) {
        hi[j] = __float2bfloat16_rn(xs[j]);
        lo[j] = __float2bfloat16_rn(xs[j] - __bfloat162float(hi[j]));
    }
    __nv_bfloat162 h01, h23, l01, l23;
    h01.x = hi[0]; h01.y = hi[1]; h23.x = hi[2]; h23.y = hi[3];
    l01.x = lo[0]; l01.y = lo[1]; l23.x = lo[2]; l23.y = lo[3];
    __nv_bfloat16* b = Ap + (size_t)m * 3 * K;
    *reinterpret_cast<__nv_bfloat162*>(b + k) = h01;
    *reinterpret_cast<__nv_bfloat162*>(b + k + 2) = h23;
    *reinterpret_cast<__nv_bfloat162*>(b + K + k) = l01;
    *reinterpret_cast<__nv_bfloat162*>(b + K + k + 2) = l23;
    *reinterpret_cast<__nv_bfloat162*>(b + 2 * K + k) = h01;
    *reinterpret_cast<__nv_bfloat162*>(b + 2 * K + k + 2) = h23;
}
// B' = [hi | hi | lo]  (N x 3K) transposed from fp32 W (K x N)
__global__ void conv_wt_kernel(const float* __restrict__ W, __nv_bfloat16* __restrict__ Bp,
                               int K, int N)
{
    int idx = blockIdx.x * blockDim.x + threadIdx.x;
    if (idx >= K * N) return;
    int k = idx % K;
    int n = idx / K;
    float x = W[(size_t)k * N + n];
    __nv_bfloat16 hi = __float2bfloat16_rn(x);
    __nv_bfloat16 lo = __float2bfloat16_rn(x - __bfloat162float(hi));
    __nv_bfloat16* b = Bp + (size_t)n * 3 * K;
    b[k] = hi;
    b[K + k] = hi;
    b[2 * K + k] = lo;
}

// ---------------- attention score ----------------
__global__ __launch_bounds__(256) void ascore_kernel(
    const float* __restrict__ h, const float* __restrict__ attS,
    const float* __restrict__ attD, float* __restrict__ aS, float* __restrict__ aD,
    int N, int Ndst, int HC, int C)
{
    int n = blockIdx.x;
    int warp = threadIdx.x >> 5;
    int lane = threadIdx.x & 31;
    const float* hp = h + (size_t)n * HC + warp * C;
    const float* sp = attS + warp * C;
    const float* dp = attD + warp * C;
    float vs = 0.f, vd = 0.f;
    for (int c = lane; c < C; c += 32) {
        float x = hp[c];
        vs = fmaf(x, sp[c], vs);
        vd = fmaf(x, dp[c], vd);
    }
#pragma unroll
    for (int off = 16; off > 0; off >>= 1) {
        vs += __shfl_xor_sync(0xffffffffu, vs, off);
        vd += __shfl_xor_sync(0xffffffffu, vd, off);
    }
    if (lane == 0) {
        aS[n * 8 + warp] = vs;
        if (n < Ndst) aD[n * 8 + warp] = vd;
    }
}

// ---------------- CSR build ----------------
__global__ void zero_int_kernel(int* p, int n) {
    int i = blockIdx.x * blockDim.x + threadIdx.x;
    if (i < n) p[i] = 0;
}
__global__ void hist_kernel(const int* __restrict__ dst, int E, int* __restrict__ deg) {
    int i = blockIdx.x * blockDim.x + threadIdx.x;
    if (i < E) atomicAdd(&deg[dst[i]], 1);
}
__global__ __launch_bounds__(1024) void scan_kernel(
    const int* __restrict__ deg, int* __restrict__ rowptr, int* __restrict__ cursor, int n)
{
    __shared__ int sh[1024];
    int t = threadIdx.x;
    int per = (n + 1023) >> 10;
    int lo = t * per;
    int hi = min(lo + per, n);
    int s = 0;
    for (int i = lo; i < hi; i++) s += deg[i];
    sh[t] = s;
    __syncthreads();
    for (int off = 1; off < 1024; off <<= 1) {
        int v = (t >= off) ? sh[t - off] : 0;
        __syncthreads();
        sh[t] += v;
        __syncthreads();
    }
    int run = (t == 0) ? 0 : sh[t - 1];
    for (int i = lo; i < hi; i++) {
        rowptr[i] = run;
        cursor[i] = run;
        run += deg[i];
    }
    if (t == 0) rowptr[n] = sh[1023];
}
__global__ void scatter_kernel(const int* __restrict__ src, const int* __restrict__ dst,
                               int E, int* __restrict__ cursor, int* __restrict__ col)
{
    int i = blockIdx.x * blockDim.x + threadIdx.x;
    if (i < E) {
        int p = atomicAdd(&cursor[dst[i]], 1);
        col[p] = src[i];
    }
}

// ---------------- layer 1 fused softmax + aggregate + bias + ELU ----------------
__global__ __launch_bounds__(128) void agg1_kernel(
    const float* __restrict__ h1, const float* __restrict__ asrc,
    const float* __restrict__ adst, const int* __restrict__ rowptr,
    const int* __restrict__ col, const float* __restrict__ bias,
    float* __restrict__ x1)
{
    const int n = blockIdx.x;
    const int t = threadIdx.x;
    const int warp = t >> 5, lane = t & 31;
    __shared__ float sadst[8], sm[8], ss[8];
    __shared__ float red[4][8];
    __shared__ float salpha[16 * 8];
    __shared__ int scol[16];

    const int start = rowptr[n], end = rowptr[n + 1];
    if (t < 8) sadst[t] = adst[n * 8 + t];
    __syncthreads();

    float lm[8];
#pragma unroll
    for (int h = 0; h < 8; h++) lm[h] = -1e30f;
    for (int j = start + t; j < end; j += 128) {
        const float* ap = asrc + (size_t)col[j] * 8;
#pragma unroll
        for (int h = 0; h < 8; h++) {
            float e = ap[h] + sadst[h];
            e = e > 0.f ? e : NEG_SLOPE * e;
            lm[h] = fmaxf(lm[h], e);
        }
    }
#pragma unroll
    for (int h = 0; h < 8; h++)
#pragma unroll
        for (int off = 16; off > 0; off >>= 1)
            lm[h] = fmaxf(lm[h], __shfl_xor_sync(0xffffffffu, lm[h], off));
    if (lane == 0)
#pragma unroll
        for (int h = 0; h < 8; h++) red[warp][h] = lm[h];
    __syncthreads();
    if (t < 8) sm[t] = fmaxf(fmaxf(red[0][t], red[1][t]), fmaxf(red[2][t], red[3][t]));
    __syncthreads();

    float lsum[8];
#pragma unroll
    for (int h = 0; h < 8; h++) lsum[h] = 0.f;
    for (int j = start + t; j < end; j += 128) {
        const float* ap = asrc + (size_t)col[j] * 8;
#pragma unroll
        for (int h = 0; h < 8; h++) {
            float e = ap[h] + sadst[h];
            e = e > 0.f ? e : NEG_SLOPE * e;
            lsum[h] += expf(e - sm[h]);
        }
    }
#pragma unroll
    for (int h = 0; h < 8; h++)
#pragma unroll
        for (int off = 16; off > 0; off >>= 1)
            lsum[h] += __shfl_xor_sync(0xffffffffu, lsum[h], off);
    if (lane == 0)
#pragma unroll
        for (int h = 0; h < 8; h++) red[warp][h] = lsum[h];
    __syncthreads();
    if (t < 8) ss[t] = red[0][t] + red[1][t] + red[2][t] + red[3][t];
    __syncthreads();

    float acc0 = 0.f, acc1 = 0.f, acc2 = 0.f, acc3 = 0.f;
    const int head = t >> 4;
    const int c4 = t << 2;
    for (int base = start; base < end; base += 16) {
        int cnt = min(16, end - base);
        if (t < cnt) scol[t] = col[base + t];
        if (t < cnt * 8) {
            int j = base + (t >> 3);
            int h = t & 7;
            float e = asrc[(size_t)col[j] * 8 + h] + sadst[h];
            e = e > 0.f ? e : NEG_SLOPE * e;
            salpha[t] = expf(e - sm[h]) / ss[h];
        }
        __syncthreads();
        for (int q = 0; q < cnt; q++) {
            int s = scol[q];
            float a = salpha[q * 8 + head];
            float4 v = *reinterpret_cast<const float4*>(h1 + (size_t)s * HC1 + c4);
            acc0 = fmaf(a, v.x, acc0);
            acc1 = fmaf(a, v.y, acc1);
            acc2 = fmaf(a, v.z, acc2);
            acc3 = fmaf(a, v.w, acc3);
        }
        __syncthreads();
    }
    float o[4] = {acc0, acc1, acc2, acc3};
#pragma unroll
    for (int i = 0; i < 4; i++) {
        float v = o[i] + bias[c4 + i];
        v = v > 0.f ? v : expm1f(v);
        x1[(size_t)n * HC1 + c4 + i] = v;
    }
}

// ---------------- layer 2 fused softmax + aggregate + head-mean + bias ----------------
__global__ __launch_bounds__(256) void agg2_kernel(
    const float* __restrict__ h2, const float* __restrict__ asrc,
    const float* __restrict__ adst, const int* __restrict__ rowptr,
    const int* __restrict__ col, const float* __restrict__ bias,
    float* __restrict__ out)
{
    const int n = blockIdx.x;
    const int t = threadIdx.x;
    const int warp = t >> 5, lane = t & 31;
    __shared__ float sadst[8], sm[8], ss[8];
    __shared__ float red[8][8];
    __shared__ float salpha[32 * 8];
    __shared__ int scol[32];

    const int start = rowptr[n], end = rowptr[n + 1];
    if (t < 8) sadst[t] = adst[n * 8 + t];
    __syncthreads();

    float lm[8];
#pragma unroll
    for (int h = 0; h < 8; h++) lm[h] = -1e30f;
    for (int j = start + t; j < end; j += 256) {
        const float* ap = asrc + (size_t)col[j] * 8;
#pragma unroll
        for (int h = 0; h < 8; h++) {
            float e = ap[h] + sadst[h];
            e = e > 0.f ? e : NEG_SLOPE * e;
            lm[h] = fmaxf(lm[h], e);
        }
    }
#pragma unroll
    for (int h = 0; h < 8; h++)
#pragma unroll
        for (int off = 16; off > 0; off >>= 1)
            lm[h] = fmaxf(lm[h], __shfl_xor_sync(0xffffffffu, lm[h], off));
    if (lane == 0)
#pragma unroll
        for (int h = 0; h < 8; h++) red[warp][h] = lm[h];
    __syncthreads();
    if (t < 8) {
        float m = red[0][t];
#pragma unroll
        for (int w = 1; w < 8; w++) m = fmaxf(m, red[w][t]);
        sm[t] = m;
    }
    __syncthreads();

    float lsum[8];
#pragma unroll
    for (int h = 0; h < 8; h++) lsum[h] = 0.f;
    for (int j = start + t; j < end; j += 256) {
        const float* ap = asrc + (size_t)col[j] * 8;
#pragma unroll
        for (int h = 0; h < 8; h++) {
            float e = ap[h] + sadst[h];
            e = e > 0.f ? e : NEG_SLOPE * e;
            lsum[h] += expf(e - sm[h]);
        }
    }
#pragma unroll
    for (int h = 0; h < 8; h++)
#pragma unroll
        for (int off = 16; off > 0; off >>= 1)
            lsum[h] += __shfl_xor_sync(0xffffffffu, lsum[h], off);
    if (lane == 0)
#pragma unroll
        for (int h = 0; h < 8; h++) red[warp][h] = lsum[h];
    __syncthreads();
    if (t < 8) {
        float s = 0.f;
#pragma unroll
        for (int w = 0; w < 8; w++) s += red[w][t];
        ss[t] = s;
    }
    __syncthreads();

    float acc[8];
#pragma unroll
    for (int h = 0; h < 8; h++) acc[h] = 0.f;
    for (int base = start; base < end; base += 32) {
        int cnt = min(32, end - base);
        if (t < cnt) scol[t] = col[base + t];
        if (t < cnt * 8) {
            int j = base + (t >> 3);
            int h = t & 7;
            float e = asrc[(size_t)col[j] * 8 + h] + sadst[h];
            e = e > 0.f ? e : NEG_SLOPE * e;
            salpha[t] = expf(e - sm[h]) / ss[h];
        }
        __syncthreads();
        for (int q = 0; q < cnt; q++) {
            const float* hp = h2 + (size_t)scol[q] * HC2 + t;
#pragma unroll
            for (int h = 0; h < 8; h++)
                acc[h] = fmaf(salpha[q * 8 + h], hp[h * C2], acc[h]);
        }
        __syncthreads();
    }
    float s = 0.f;
#pragma unroll
    for (int h = 0; h < 8; h++) s += acc[h];
    out[(size_t)n * C2 + t] = 0.125f * s + bias[t];
}

// ---------------- host ----------------
extern "C" void kernel_launch(void* const* d_in, const int* in_sizes, int n_in,
                              void* d_out, int out_size)
{
    const float* x        = (const float*)d_in[0];
    const int*   src1     = (const int*)d_in[1];
    const int*   dst1     = (const int*)d_in[2];
    const int*   src2     = (const int*)d_in[3];
    const int*   dst2     = (const int*)d_in[4];
    const float* W1       = (const float*)d_in[5];
    const float* att_src1 = (const float*)d_in[6];
    const float* att_dst1 = (const float*)d_in[7];
    const float* b1       = (const float*)d_in[8];
    const float* W2       = (const float*)d_in[9];
    const float* att_src2 = (const float*)d_in[10];
    const float* att_dst2 = (const float*)d_in[11];
    const float* b2       = (const float*)d_in[12];
    float* out = (float*)d_out;

    const int E1 = in_sizes[1];
    const int E2 = in_sizes[3];

    float *h1, *x1, *h2, *as1, *ad1, *as2, *ad2;
    int *deg1, *rp1, *cur1, *col1, *deg2, *rp2, *cur2, *col2;
    __nv_bfloat16 *a1p, *b1p, *a2p, *b2p;
    cudaGetSymbolAddress((void**)&h1, g_h1);
    cudaGetSymbolAddress((void**)&x1, g_x1);
    cudaGetSymbolAddress((void**)&h2, g_h2);
    cudaGetSymbolAddress((void**)&as1, g_as1);
    cudaGetSymbolAddress((void**)&ad1, g_ad1);
    cudaGetSymbolAddress((void**)&as2, g_as2);
    cudaGetSymbolAddress((void**)&ad2, g_ad2);
    cudaGetSymbolAddress((void**)&deg1, g_deg1);
    cudaGetSymbolAddress((void**)&rp1, g_rp1);
    cudaGetSymbolAddress((void**)&cur1, g_cur1);
    cudaGetSymbolAddress((void**)&col1, g_col1);
    cudaGetSymbolAddress((void**)&deg2, g_deg2);
    cudaGetSymbolAddress((void**)&rp2, g_rp2);
    cudaGetSymbolAddress((void**)&cur2, g_cur2);
    cudaGetSymbolAddress((void**)&col2, g_col2);
    cudaGetSymbolAddress((void**)&a1p, g_a1p);
    cudaGetSymbolAddress((void**)&b1p, g_b1p);
    cudaGetSymbolAddress((void**)&a2p, g_a2p);
    cudaGetSymbolAddress((void**)&b2p, g_b2p);

    cudaFuncSetAttribute(gemm_mma, cudaFuncAttributeMaxDynamicSharedMemorySize, SMEM_GEMM);

    // ---- layer 1 ----
    {
        size_t tot = (size_t)N0 * (D / 4);
        conv_split_kernel<<<(unsigned)((tot + 255) / 256), 256>>>(x, a1p, N0, D);
    }
    conv_wt_kernel<<<(D * HC1 + 255) / 256, 256>>>(W1, b1p, D, HC1);
    {
        dim3 grid(HC1 / 128, (N0 + 127) / 128);
        gemm_mma<<<grid, 256, SMEM_GEMM>>>(a1p, b1p, h1, N0, HC1, KP1);
    }
    ascore_kernel<<<N0, 256>>>(h1, att_src1, att_dst1, as1, ad1, N0, N1, HC1, C1);

    zero_int_kernel<<<(N1 + 255) / 256, 256>>>(deg1, N1);
    hist_kernel<<<(E1 + 255) / 256, 256>>>(dst1, E1, deg1);
    scan_kernel<<<1, 1024>>>(deg1, rp1, cur1, N1);
    scatter_kernel<<<(E1 + 255) / 256, 256>>>(src1, dst1, E1, cur1, col1);

    agg1_kernel<<<N1, 128>>>(h1, as1, ad1, rp1, col1, b1, x1);

    // ---- layer 2 ----
    {
        size_t tot = (size_t)N1 * (HC1 / 4);
        conv_split_kernel<<<(unsigned)((tot + 255) / 256), 256>>>(x1, a2p, N1, HC1);
    }
    conv_wt_kernel<<<(HC1 * HC2 + 255) / 256, 256>>>(W2, b2p, HC1, HC2);
    {
        dim3 grid(HC2 / 128, (N1 + 127) / 128);
        gemm_mma<<<grid, 256, SMEM_GEMM>>>(a2p, b2p, h2, N1, HC2, KP2);
    }
    ascore_kernel<<<N1, 256>>>(h2, att_src2, att_dst2, as2, ad2, N1, N2, HC2, C2);

    zero_int_kernel<<<(N2 + 255) / 256, 256>>>(deg2, N2);
    hist_kernel<<<(E2 + 255) / 256, 256>>>(dst2, E2, deg2);
    scan_kernel<<<1, 1024>>>(deg2, rp2, cur2, N2);
    scatter_kernel<<<(E2 + 255) / 256, 256>>>(src2, dst2, E2, cur2, col2);

    agg2_kernel<<<N2, 256>>>(h2, as2, ad2, rp2, col2, b2, out);

    (void)n_in; (void)out_size;
}

// round 4
// speedup vs baseline: 2.3450x; 1.1374x over previous
#include <cuda_runtime.h>
#include <cuda_bf16.h>
#include <cstdint>
#include <math.h>

// ---------------- problem constants ----------------
#define N0 120000
#define N1 24000
#define N2 6000
#define D  256
#define H1 8
#define C1 64
#define HC1 (H1*C1)     // 512
#define H2 8
#define C2 256
#define HC2 (H2*C2)     // 2048
#define E1MAX 384000
#define E2MAX 96000
#define NEG_SLOPE 0.2f

#define KS1 (2*D)       // 512  A'/B' storage K (hi|lo)
#define KS2 (2*HC1)     // 1024

// ---------------- scratch (static device globals; no allocation) ----------------
__device__ float g_h1[(size_t)N0 * HC1];     // 245.8 MB
__device__ float g_x1[(size_t)N1 * HC1];     //  49.2 MB
__device__ float g_h2[(size_t)N1 * HC2];     // 196.6 MB
__device__ float g_as1[(size_t)N0 * H1];
__device__ float g_ad1[(size_t)N1 * H1];
__device__ float g_as2[(size_t)N1 * H2];
__device__ float g_ad2[(size_t)N2 * H2];
__device__ int g_deg1[N1];
__device__ int g_rp1[N1 + 1];
__device__ int g_cur1[N1];
__device__ int g_col1[E1MAX];
__device__ int g_deg2[N2];
__device__ int g_rp2[N2 + 1];
__device__ int g_cur2[N2];
__device__ int g_col2[E2MAX];
// split-precision bf16 operands [hi|lo]
__device__ __nv_bfloat16 g_a1p[(size_t)N0 * KS1];   // 122.9 MB
__device__ __nv_bfloat16 g_b1p[(size_t)HC1 * KS1];  //  0.5 MB
__device__ __nv_bfloat16 g_a2p[(size_t)N1 * KS2];   //  49.2 MB
__device__ __nv_bfloat16 g_b2p[(size_t)HC2 * KS2];  //  4.2 MB

// ================= PTX helpers =================
__device__ __forceinline__ uint32_t smem_u32(const void* p) {
    uint32_t a;
    asm("{ .reg .u64 t; cvta.to.shared.u64 t, %1; cvt.u32.u64 %0, t; }" : "=r"(a) : "l"(p));
    return a;
}
#define CP_ASYNC16(sp, gp) \
    asm volatile("cp.async.cg.shared.global [%0], [%1], 16;" :: "r"(sp), "l"(gp) : "memory")
#define CP_COMMIT() asm volatile("cp.async.commit_group;" ::: "memory")
#define CP_WAIT(n)  asm volatile("cp.async.wait_group %0;" :: "n"(n) : "memory")
#define LDMX4(r, addr) \
    asm volatile("ldmatrix.sync.aligned.m8n8.x4.shared.b16 {%0,%1,%2,%3}, [%4];" \
        : "=r"((r)[0]), "=r"((r)[1]), "=r"((r)[2]), "=r"((r)[3]) : "r"(addr))
#define MMA16816(d, a, b0v, b1v) \
    asm volatile("mma.sync.aligned.m16n8k16.row.col.f32.bf16.bf16.f32 " \
        "{%0,%1,%2,%3}, {%4,%5,%6,%7}, {%8,%9}, {%0,%1,%2,%3};" \
        : "+f"((d)[0]), "+f"((d)[1]), "+f"((d)[2]), "+f"((d)[3]) \
        : "r"((a)[0]), "r"((a)[1]), "r"((a)[2]), "r"((a)[3]), "r"(b0v), "r"(b1v))

// ================= bf16 mma.sync GEMM with 3-term split remap + fused ascore epilogue ====
// A stored [M, 2K] = [hi|lo], B stored [Nfull, 2K] = [hi|lo].
// Logical chunks c in [0, 3K/64): terms hi*hi, lo*hi, hi*lo.
// CTA tile 128x128, 256 thr = 4(M) x 2(N) warps, warp tile 32x64, 3-stage cp.async.
#define STAGE_BYTES 32768
#define SMEM_GEMM   (3 * STAGE_BYTES)

__device__ __forceinline__ void gemm_load_stage(
    const __nv_bfloat16* __restrict__ A, const __nv_bfloat16* __restrict__ B,
    int M, int Kst, int K64, int bm, int bn, int c, uint32_t stbase, int tid)
{
    const int aoff = (c < 2 * K64) ? c : c - 2 * K64;   // hi, lo, hi
    const int boff = (c < K64) ? c : c - K64;           // hi, hi, lo
    const int r0 = tid >> 3;
    const int kseg = tid & 7;
    const uint32_t abase = stbase;
    const uint32_t bbase = stbase + 16384;
#pragma unroll
    for (int i = 0; i < 4; i++) {
        int row = r0 + i * 32;
        int grow = bm + row; if (grow >= M) grow = M - 1;
        const void* gp = (const void*)(A + (size_t)grow * Kst + aoff * 64 + kseg * 8);
        uint32_t sp = abase + (uint32_t)(row * 128) + ((uint32_t)(kseg * 16) ^ (uint32_t)((row & 7) << 4));
        CP_ASYNC16(sp, gp);
    }
#pragma unroll
    for (int i = 0; i < 4; i++) {
        int row = r0 + i * 32;
        const void* gp = (const void*)(B + (size_t)(bn + row) * Kst + boff * 64 + kseg * 8);
        uint32_t sp = bbase + (uint32_t)(row * 128) + ((uint32_t)(kseg * 16) ^ (uint32_t)((row & 7) << 4));
        CP_ASYNC16(sp, gp);
    }
}

__global__ __launch_bounds__(256, 2) void gemm_mma(
    const __nv_bfloat16* __restrict__ A, const __nv_bfloat16* __restrict__ B,
    float* __restrict__ C, int M, int Nfull, int Kst,
    const float* __restrict__ attS, const float* __restrict__ attD,
    float* __restrict__ aS, float* __restrict__ aD, int Chead, int Ndst)
{
    extern __shared__ __align__(1024) char smem[];
    const uint32_t sb = smem_u32(smem);
    const int tid = threadIdx.x;
    const int lane = tid & 31, wid = tid >> 5;
    const int wm = wid & 3, wn = wid >> 2;
    const int bm = blockIdx.y * 128, bn = blockIdx.x * 128;

    int arow[2], asw[2];
#pragma unroll
    for (int mi = 0; mi < 2; mi++) {
        int r = wm * 32 + mi * 16 + (lane & 7) + ((lane >> 3) & 1) * 8;
        arow[mi] = r * 128;
        asw[mi] = (r & 7) << 4;
    }
    const uint32_t akadd = ((lane >> 4) & 1) * 16;
    int brow[4], bsw[4];
#pragma unroll
    for (int nb = 0; nb < 4; nb++) {
        int r = wn * 64 + nb * 16 + ((lane >> 4) & 1) * 8 + (lane & 7);
        brow[nb] = r * 128;
        bsw[nb] = (r & 7) << 4;
    }
    const uint32_t bkadd = ((lane >> 3) & 1) * 16;

    float acc[2][8][4];
#pragma unroll
    for (int mi = 0; mi < 2; mi++)
#pragma unroll
        for (int ni = 0; ni < 8; ni++)
#pragma unroll
            for (int q = 0; q < 4; q++) acc[mi][ni][q] = 0.f;

    const int K64 = Kst >> 7;        // K/64
    const int nch = 3 * K64;

    gemm_load_stage(A, B, M, Kst, K64, bm, bn, 0, sb, tid); CP_COMMIT();
    gemm_load_stage(A, B, M, Kst, K64, bm, bn, 1, sb + STAGE_BYTES, tid); CP_COMMIT();

    for (int c = 0; c < nch; c++) {
        if (c + 2 < nch) {
            gemm_load_stage(A, B, M, Kst, K64, bm, bn, c + 2, sb + ((c + 2) % 3) * STAGE_BYTES, tid);
            CP_COMMIT();
            CP_WAIT(2);
        } else if (c + 1 < nch) {
            CP_WAIT(1);
        } else {
            CP_WAIT(0);
        }
        __syncthreads();

        const uint32_t abase = sb + (c % 3) * STAGE_BYTES;
        const uint32_t bbase = abase + 16384;
#pragma unroll
        for (int ks = 0; ks < 4; ks++) {
            const uint32_t k0b = ks * 32;
            uint32_t af[2][4];
#pragma unroll
            for (int mi = 0; mi < 2; mi++) {
                uint32_t addr = abase + arow[mi] + ((k0b + akadd) ^ (uint32_t)asw[mi]);
                LDMX4(af[mi], addr);
            }
            uint32_t bf[4][4];
#pragma unroll
            for (int nb = 0; nb < 4; nb++) {
                uint32_t addr = bbase + brow[nb] + ((k0b + bkadd) ^ (uint32_t)bsw[nb]);
                LDMX4(bf[nb], addr);
            }
#pragma unroll
            for (int mi = 0; mi < 2; mi++)
#pragma unroll
                for (int ni = 0; ni < 8; ni++) {
                    const int nb = ni >> 1, hf = ni & 1;
                    MMA16816(acc[mi][ni], af[mi], bf[nb][hf * 2], bf[nb][hf * 2 + 1]);
                }
        }
        __syncthreads();
    }

    // ---- epilogue: store C + fused attention scores ----
    const int crow0 = bm + wm * 32 + (lane >> 2);
    const int ccol0 = bn + wn * 64 + (lane & 3) * 2;
    const int head = (bn + wn * 64) / Chead;

    // per-(mi,hf) row partial dots with att vectors
    float psrc[2][2], pdst[2][2];
#pragma unroll
    for (int mi = 0; mi < 2; mi++)
#pragma unroll
        for (int hf = 0; hf < 2; hf++) { psrc[mi][hf] = 0.f; pdst[mi][hf] = 0.f; }
#pragma unroll
    for (int ni = 0; ni < 8; ni++) {
        int gc = ccol0 + ni * 8;
        float s0 = attS[gc], s1 = attS[gc + 1];
        float d0 = attD[gc], d1 = attD[gc + 1];
#pragma unroll
        for (int mi = 0; mi < 2; mi++)
#pragma unroll
            for (int hf = 0; hf < 2; hf++) {
                psrc[mi][hf] = fmaf(acc[mi][ni][hf * 2], s0, fmaf(acc[mi][ni][hf * 2 + 1], s1, psrc[mi][hf]));
                pdst[mi][hf] = fmaf(acc[mi][ni][hf * 2], d0, fmaf(acc[mi][ni][hf * 2 + 1], d1, pdst[mi][hf]));
            }
    }
    // reduce across the 4 lanes sharing a row (lane&3 varies col only)
#pragma unroll
    for (int mi = 0; mi < 2; mi++)
#pragma unroll
        for (int hf = 0; hf < 2; hf++) {
#pragma unroll
            for (int off = 1; off < 4; off <<= 1) {
                psrc[mi][hf] += __shfl_xor_sync(0xffffffffu, psrc[mi][hf], off);
                pdst[mi][hf] += __shfl_xor_sync(0xffffffffu, pdst[mi][hf], off);
            }
        }
    if ((lane & 3) == 0) {
#pragma unroll
        for (int mi = 0; mi < 2; mi++)
#pragma unroll
            for (int hf = 0; hf < 2; hf++) {
                int row = crow0 + mi * 16 + hf * 8;
                if (row < M) {
                    atomicAdd(&aS[(size_t)row * 8 + head], psrc[mi][hf]);
                    if (row < Ndst) atomicAdd(&aD[(size_t)row * 8 + head], pdst[mi][hf]);
                }
            }
    }

#pragma unroll
    for (int mi = 0; mi < 2; mi++)
#pragma unroll
        for (int hf = 0; hf < 2; hf++) {
            int row = crow0 + mi * 16 + hf * 8;
            if (row < M) {
                float* cp = C + (size_t)row * Nfull + ccol0;
#pragma unroll
                for (int ni = 0; ni < 8; ni++) {
                    float2 v = make_float2(acc[mi][ni][hf * 2], acc[mi][ni][hf * 2 + 1]);
                    *reinterpret_cast<float2*>(cp + ni * 8) = v;
                }
            }
        }
}

// ---------------- split-precision conversions ----------------
// A' = [hi | lo]  (M x 2K) from fp32 X (M x K)
__global__ void conv_split_kernel(const float* __restrict__ X, __nv_bfloat16* __restrict__ Ap,
                                  int M, int K)
{
    size_t i = (size_t)blockIdx.x * blockDim.x + threadIdx.x;
    int kq = K >> 2;
    size_t total = (size_t)M * kq;
    if (i >= total) return;
    int m = (int)(i / kq);
    int k = (int)(i - (size_t)m * kq) << 2;
    float4 v = *reinterpret_cast<const float4*>(X + (size_t)m * K + k);
    float xs[4] = {v.x, v.y, v.z, v.w};
    __nv_bfloat16 hi[4], lo[4];
#pragma unroll
    for (int j = 0; j < 4; j++) {
        hi[j] = __float2bfloat16_rn(xs[j]);
        lo[j] = __float2bfloat16_rn(xs[j] - __bfloat162float(hi[j]));
    }
    __nv_bfloat162 h01, h23, l01, l23;
    h01.x = hi[0]; h01.y = hi[1]; h23.x = hi[2]; h23.y = hi[3];
    l01.x = lo[0]; l01.y = lo[1]; l23.x = lo[2]; l23.y = lo[3];
    __nv_bfloat16* b = Ap + (size_t)m * 2 * K;
    *reinterpret_cast<__nv_bfloat162*>(b + k) = h01;
    *reinterpret_cast<__nv_bfloat162*>(b + k + 2) = h23;
    *reinterpret_cast<__nv_bfloat162*>(b + K + k) = l01;
    *reinterpret_cast<__nv_bfloat162*>(b + K + k + 2) = l23;
}
// B' = [hi | lo]  (N x 2K) transposed from fp32 W (K x N)
__global__ void conv_wt_kernel(const float* __restrict__ W, __nv_bfloat16* __restrict__ Bp,
                               int K, int N)
{
    int idx = blockIdx.x * blockDim.x + threadIdx.x;
    if (idx >= K * N) return;
    int k = idx % K;
    int n = idx / K;
    float x = W[(size_t)k * N + n];
    __nv_bfloat16 hi = __float2bfloat16_rn(x);
    __nv_bfloat16 lo = __float2bfloat16_rn(x - __bfloat162float(hi));
    __nv_bfloat16* b = Bp + (size_t)n * 2 * K;
    b[k] = hi;
    b[K + k] = lo;
}

__global__ void zero_float_kernel(float* p, int n) {
    int i = blockIdx.x * blockDim.x + threadIdx.x;
    if (i < n) p[i] = 0.f;
}

// ---------------- CSR build ----------------
__global__ void zero_int_kernel(int* p, int n) {
    int i = blockIdx.x * blockDim.x + threadIdx.x;
    if (i < n) p[i] = 0;
}
__global__ void hist_kernel(const int* __restrict__ dst, int E, int* __restrict__ deg) {
    int i = blockIdx.x * blockDim.x + threadIdx.x;
    if (i < E) atomicAdd(&deg[dst[i]], 1);
}
__global__ __launch_bounds__(1024) void scan_kernel(
    const int* __restrict__ deg, int* __restrict__ rowptr, int* __restrict__ cursor, int n)
{
    __shared__ int sh[1024];
    int t = threadIdx.x;
    int per = (n + 1023) >> 10;
    int lo = t * per;
    int hi = min(lo + per, n);
    int s = 0;
    for (int i = lo; i < hi; i++) s += deg[i];
    sh[t] = s;
    __syncthreads();
    for (int off = 1; off < 1024; off <<= 1) {
        int v = (t >= off) ? sh[t - off] : 0;
        __syncthreads();
        sh[t] += v;
        __syncthreads();
    }
    int run = (t == 0) ? 0 : sh[t - 1];
    for (int i = lo; i < hi; i++) {
        rowptr[i] = run;
        cursor[i] = run;
        run += deg[i];
    }
    if (t == 0) rowptr[n] = sh[1023];
}
__global__ void scatter_kernel(const int* __restrict__ src, const int* __restrict__ dst,
                               int E, int* __restrict__ cursor, int* __restrict__ col)
{
    int i = blockIdx.x * blockDim.x + threadIdx.x;
    if (i < E) {
        int p = atomicAdd(&cursor[dst[i]], 1);
        col[p] = src[i];
    }
}

// ---------------- layer 1 fused softmax + aggregate + bias + ELU ----------------
__global__ __launch_bounds__(128) void agg1_kernel(
    const float* __restrict__ h1, const float* __restrict__ asrc,
    const float* __restrict__ adst, const int* __restrict__ rowptr,
    const int* __restrict__ col, const float* __restrict__ bias,
    float* __restrict__ x1)
{
    const int n = blockIdx.x;
    const int t = threadIdx.x;
    const int warp = t >> 5, lane = t & 31;
    __shared__ float sadst[8], sm[8], ss[8];
    __shared__ float red[4][8];
    __shared__ float salpha[16 * 8];
    __shared__ int scol[16];

    const int start = rowptr[n], end = rowptr[n + 1];
    if (t < 8) sadst[t] = adst[n * 8 + t];
    __syncthreads();

    float lm[8];
#pragma unroll
    for (int h = 0; h < 8; h++) lm[h] = -1e30f;
    for (int j = start + t; j < end; j += 128) {
        const float* ap = asrc + (size_t)col[j] * 8;
#pragma unroll
        for (int h = 0; h < 8; h++) {
            float e = ap[h] + sadst[h];
            e = e > 0.f ? e : NEG_SLOPE * e;
            lm[h] = fmaxf(lm[h], e);
        }
    }
#pragma unroll
    for (int h = 0; h < 8; h++)
#pragma unroll
        for (int off = 16; off > 0; off >>= 1)
            lm[h] = fmaxf(lm[h], __shfl_xor_sync(0xffffffffu, lm[h], off));
    if (lane == 0)
#pragma unroll
        for (int h = 0; h < 8; h++) red[warp][h] = lm[h];
    __syncthreads();
    if (t < 8) sm[t] = fmaxf(fmaxf(red[0][t], red[1][t]), fmaxf(red[2][t], red[3][t]));
    __syncthreads();

    float lsum[8];
#pragma unroll
    for (int h = 0; h < 8; h++) lsum[h] = 0.f;
    for (int j = start + t; j < end; j += 128) {
        const float* ap = asrc + (size_t)col[j] * 8;
#pragma unroll
        for (int h = 0; h < 8; h++) {
            float e = ap[h] + sadst[h];
            e = e > 0.f ? e : NEG_SLOPE * e;
            lsum[h] += expf(e - sm[h]);
        }
    }
#pragma unroll
    for (int h = 0; h < 8; h++)
#pragma unroll
        for (int off = 16; off > 0; off >>= 1)
            lsum[h] += __shfl_xor_sync(0xffffffffu, lsum[h], off);
    if (lane == 0)
#pragma unroll
        for (int h = 0; h < 8; h++) red[warp][h] = lsum[h];
    __syncthreads();
    if (t < 8) ss[t] = red[0][t] + red[1][t] + red[2][t] + red[3][t];
    __syncthreads();

    float acc0 = 0.f, acc1 = 0.f, acc2 = 0.f, acc3 = 0.f;
    const int head = t >> 4;
    const int c4 = t << 2;
    for (int base = start; base < end; base += 16) {
        int cnt = min(16, end - base);
        if (t < cnt) scol[t] = col[base + t];
        if (t < cnt * 8) {
            int j = base + (t >> 3);
            int h = t & 7;
            float e = asrc[(size_t)col[j] * 8 + h] + sadst[h];
            e = e > 0.f ? e : NEG_SLOPE * e;
            salpha[t] = expf(e - sm[h]) / ss[h];
        }
        __syncthreads();
        for (int q = 0; q < cnt; q++) {
            int s = scol[q];
            float a = salpha[q * 8 + head];
            float4 v = *reinterpret_cast<const float4*>(h1 + (size_t)s * HC1 + c4);
            acc0 = fmaf(a, v.x, acc0);
            acc1 = fmaf(a, v.y, acc1);
            acc2 = fmaf(a, v.z, acc2);
            acc3 = fmaf(a, v.w, acc3);
        }
        __syncthreads();
    }
    float o[4] = {acc0, acc1, acc2, acc3};
#pragma unroll
    for (int i = 0; i < 4; i++) {
        float v = o[i] + bias[c4 + i];
        v = v > 0.f ? v : expm1f(v);
        x1[(size_t)n * HC1 + c4 + i] = v;
    }
}

// ---------------- layer 2 fused softmax + aggregate + head-mean + bias ----------------
__global__ __launch_bounds__(256) void agg2_kernel(
    const float* __restrict__ h2, const float* __restrict__ asrc,
    const float* __restrict__ adst, const int* __restrict__ rowptr,
    const int* __restrict__ col, const float* __restrict__ bias,
    float* __restrict__ out)
{
    const int n = blockIdx.x;
    const int t = threadIdx.x;
    const int warp = t >> 5, lane = t & 31;
    __shared__ float sadst[8], sm[8], ss[8];
    __shared__ float red[8][8];
    __shared__ float salpha[32 * 8];
    __shared__ int scol[32];

    const int start = rowptr[n], end = rowptr[n + 1];
    if (t < 8) sadst[t] = adst[n * 8 + t];
    __syncthreads();

    float lm[8];
#pragma unroll
    for (int h = 0; h < 8; h++) lm[h] = -1e30f;
    for (int j = start + t; j < end; j += 256) {
        const float* ap = asrc + (size_t)col[j] * 8;
#pragma unroll
        for (int h = 0; h < 8; h++) {
            float e = ap[h] + sadst[h];
            e = e > 0.f ? e : NEG_SLOPE * e;
            lm[h] = fmaxf(lm[h], e);
        }
    }
#pragma unroll
    for (int h = 0; h < 8; h++)
#pragma unroll
        for (int off = 16; off > 0; off >>= 1)
            lm[h] = fmaxf(lm[h], __shfl_xor_sync(0xffffffffu, lm[h], off));
    if (lane == 0)
#pragma unroll
        for (int h = 0; h < 8; h++) red[warp][h] = lm[h];
    __syncthreads();
    if (t < 8) {
        float m = red[0][t];
#pragma unroll
        for (int w = 1; w < 8; w++) m = fmaxf(m, red[w][t]);
        sm[t] = m;
    }
    __syncthreads();

    float lsum[8];
#pragma unroll
    for (int h = 0; h < 8; h++) lsum[h] = 0.f;
    for (int j = start + t; j < end; j += 256) {
        const float* ap = asrc + (size_t)col[j] * 8;
#pragma unroll
        for (int h = 0; h < 8; h++) {
            float e = ap[h] + sadst[h];
            e = e > 0.f ? e : NEG_SLOPE * e;
            lsum[h] += expf(e - sm[h]);
        }
    }
#pragma unroll
    for (int h = 0; h < 8; h++)
#pragma unroll
        for (int off = 16; off > 0; off >>= 1)
            lsum[h] += __shfl_xor_sync(0xffffffffu, lsum[h], off);
    if (lane == 0)
#pragma unroll
        for (int h = 0; h < 8; h++) red[warp][h] = lsum[h];
    __syncthreads();
    if (t < 8) {
        float s = 0.f;
#pragma unroll
        for (int w = 0; w < 8; w++) s += red[w][t];
        ss[t] = s;
    }
    __syncthreads();

    float acc[8];
#pragma unroll
    for (int h = 0; h < 8; h++) acc[h] = 0.f;
    for (int base = start; base < end; base += 32) {
        int cnt = min(32, end - base);
        if (t < cnt) scol[t] = col[base + t];
        if (t < cnt * 8) {
            int j = base + (t >> 3);
            int h = t & 7;
            float e = asrc[(size_t)col[j] * 8 + h] + sadst[h];
            e = e > 0.f ? e : NEG_SLOPE * e;
            salpha[t] = expf(e - sm[h]) / ss[h];
        }
        __syncthreads();
        for (int q = 0; q < cnt; q++) {
            const float* hp = h2 + (size_t)scol[q] * HC2 + t;
#pragma unroll
            for (int h = 0; h < 8; h++)
                acc[h] = fmaf(salpha[q * 8 + h], hp[h * C2], acc[h]);
        }
        __syncthreads();
    }
    float s = 0.f;
#pragma unroll
    for (int h = 0; h < 8; h++) s += acc[h];
    out[(size_t)n * C2 + t] = 0.125f * s + bias[t];
}

// ---------------- host ----------------
extern "C" void kernel_launch(void* const* d_in, const int* in_sizes, int n_in,
                              void* d_out, int out_size)
{
    const float* x        = (const float*)d_in[0];
    const int*   src1     = (const int*)d_in[1];
    const int*   dst1     = (const int*)d_in[2];
    const int*   src2     = (const int*)d_in[3];
    const int*   dst2     = (const int*)d_in[4];
    const float* W1       = (const float*)d_in[5];
    const float* att_src1 = (const float*)d_in[6];
    const float* att_dst1 = (const float*)d_in[7];
    const float* b1       = (const float*)d_in[8];
    const float* W2       = (const float*)d_in[9];
    const float* att_src2 = (const float*)d_in[10];
    const float* att_dst2 = (const float*)d_in[11];
    const float* b2       = (const float*)d_in[12];
    float* out = (float*)d_out;

    const int E1 = in_sizes[1];
    const int E2 = in_sizes[3];

    float *h1, *x1, *h2, *as1, *ad1, *as2, *ad2;
    int *deg1, *rp1, *cur1, *col1, *deg2, *rp2, *cur2, *col2;
    __nv_bfloat16 *a1p, *b1p, *a2p, *b2p;
    cudaGetSymbolAddress((void**)&h1, g_h1);
    cudaGetSymbolAddress((void**)&x1, g_x1);
    cudaGetSymbolAddress((void**)&h2, g_h2);
    cudaGetSymbolAddress((void**)&as1, g_as1);
    cudaGetSymbolAddress((void**)&ad1, g_ad1);
    cudaGetSymbolAddress((void**)&as2, g_as2);
    cudaGetSymbolAddress((void**)&ad2, g_ad2);
    cudaGetSymbolAddress((void**)&deg1, g_deg1);
    cudaGetSymbolAddress((void**)&rp1, g_rp1);
    cudaGetSymbolAddress((void**)&cur1, g_cur1);
    cudaGetSymbolAddress((void**)&col1, g_col1);
    cudaGetSymbolAddress((void**)&deg2, g_deg2);
    cudaGetSymbolAddress((void**)&rp2, g_rp2);
    cudaGetSymbolAddress((void**)&cur2, g_cur2);
    cudaGetSymbolAddress((void**)&col2, g_col2);
    cudaGetSymbolAddress((void**)&a1p, g_a1p);
    cudaGetSymbolAddress((void**)&b1p, g_b1p);
    cudaGetSymbolAddress((void**)&a2p, g_a2p);
    cudaGetSymbolAddress((void**)&b2p, g_b2p);

    cudaFuncSetAttribute(gemm_mma, cudaFuncAttributeMaxDynamicSharedMemorySize, SMEM_GEMM);

    // ---- layer 1 ----
    {
        size_t tot = (size_t)N0 * (D / 4);
        conv_split_kernel<<<(unsigned)((tot + 255) / 256), 256>>>(x, a1p, N0, D);
    }
    conv_wt_kernel<<<(D * HC1 + 255) / 256, 256>>>(W1, b1p, D, HC1);
    zero_float_kernel<<<(N0 * H1 + 255) / 256, 256>>>(as1, N0 * H1);
    zero_float_kernel<<<(N1 * H1 + 255) / 256, 256>>>(ad1, N1 * H1);
    {
        dim3 grid(HC1 / 128, (N0 + 127) / 128);
        gemm_mma<<<grid, 256, SMEM_GEMM>>>(a1p, b1p, h1, N0, HC1, KS1,
                                           att_src1, att_dst1, as1, ad1, C1, N1);
    }

    zero_int_kernel<<<(N1 + 255) / 256, 256>>>(deg1, N1);
    hist_kernel<<<(E1 + 255) / 256, 256>>>(dst1, E1, deg1);
    scan_kernel<<<1, 1024>>>(deg1, rp1, cur1, N1);
    scatter_kernel<<<(E1 + 255) / 256, 256>>>(src1, dst1, E1, cur1, col1);

    agg1_kernel<<<N1, 128>>>(h1, as1, ad1, rp1, col1, b1, x1);

    // ---- layer 2 ----
    {
        size_t tot = (size_t)N1 * (HC1 / 4);
        conv_split_kernel<<<(unsigned)((tot + 255) / 256), 256>>>(x1, a2p, N1, HC1);
    }
    conv_wt_kernel<<<(HC1 * HC2 + 255) / 256, 256>>>(W2, b2p, HC1, HC2);
    zero_float_kernel<<<(N1 * H2 + 255) / 256, 256>>>(as2, N1 * H2);
    zero_float_kernel<<<(N2 * H2 + 255) / 256, 256>>>(ad2, N2 * H2);
    {
        dim3 grid(HC2 / 128, (N1 + 127) / 128);
        gemm_mma<<<grid, 256, SMEM_GEMM>>>(a2p, b2p, h2, N1, HC2, KS2,
                                           att_src2, att_dst2, as2, ad2, C2, N2);
    }

    zero_int_kernel<<<(N2 + 255) / 256, 256>>>(deg2, N2);
    hist_kernel<<<(E2 + 255) / 256, 256>>>(dst2, E2, deg2);
    scan_kernel<<<1, 1024>>>(deg2, rp2, cur2, N2);
    scatter_kernel<<<(E2 + 255) / 256, 256>>>(src2, dst2, E2, cur2, col2);

    agg2_kernel<<<N2, 256>>>(h2, as2, ad2, rp2, col2, b2, out);

    (void)n_in; (void)out_size;
}